// round 4
// baseline (speedup 1.0000x reference)
#include <cuda_runtime.h>
#include <cuda_bf16.h>
#include <math.h>

// Shapes
// x:      [8,128,64,64]
// off_w:  [27,128,3,3]
// off_b:  [27]
// w:      [128,128,3,3]
// b:      [128]
// gamma:  [128], beta: [128]
// out:    [8,128,64,64] fp32

#define NB   8
#define NC   128
#define NH   64
#define NW   64
#define NHW  4096
#define NKT  9
#define NOFF 27
#define KDIM 1152   // 128*9

// Scratch (static device allocations — allowed)
static __device__ float g_om[NB * NOFF * NHW];        // offset-conv output
static __device__ float g_wT[NKT * NC * NC];          // w transposed to [k][c][o]
static __device__ float g_y[NB * NC * NHW];           // pre-BN conv output
static __device__ float g_stats[2 * NC];              // per-channel sum, sumsq

// ---------------- packed fp32x2 helpers (Blackwell FFMA2) -------------------
__device__ __forceinline__ void ffma2(unsigned long long& d,
                                      unsigned long long a,
                                      unsigned long long b) {
    asm volatile("fma.rn.f32x2 %0, %1, %2, %0;" : "+l"(d) : "l"(a), "l"(b));
}
__device__ __forceinline__ unsigned long long bcast2(float v) {
    unsigned long long r;
    asm("mov.b64 %0, {%1, %1};" : "=l"(r) : "f"(v));
    return r;
}
__device__ __forceinline__ unsigned long long pack2(float lo, float hi) {
    unsigned long long r;
    asm("mov.b64 %0, {%1, %2};" : "=l"(r) : "f"(lo), "f"(hi));
    return r;
}
__device__ __forceinline__ float2 unpack2(unsigned long long v) {
    float2 r;
    asm("mov.b64 {%0, %1}, %2;" : "=f"(r.x), "=f"(r.y) : "l"(v));
    return r;
}

// ---------------------------------------------------------------------------
// Kernel Z: zero stats + transpose main-conv weights to [kt][c][o] layout so
// GEMM chunk loads are fully coalesced.
// ---------------------------------------------------------------------------
__global__ void prep_kernel(const float* __restrict__ w) {
    if (blockIdx.x == 0 && threadIdx.x < 2 * NC) g_stats[threadIdx.x] = 0.0f;
    int n = NKT * NC * NC;  // 147456
    for (int i = blockIdx.x * blockDim.x + threadIdx.x; i < n;
         i += gridDim.x * blockDim.x) {
        int o  = i / KDIM;
        int r  = i % KDIM;
        int c  = r / NKT;
        int kt = r % NKT;
        g_wT[(kt * NC + c) * NC + o] = w[i];
    }
}

// ---------------------------------------------------------------------------
// Kernel A: offset conv  om = conv3x3(x, off_w) + off_b   -> g_om
// Each thread handles a vertical pixel pair (lr, lr+8) packed into one f32x2
// lane; weights live in SMEM pre-duplicated as (w,w) u64 so each FFMA2 is fed
// by a single uniform-address LDS.64. 126 FFMA2 per channel per thread.
// ---------------------------------------------------------------------------
__global__ __launch_bounds__(256) void off_conv_kernel(
    const float* __restrict__ x,
    const float* __restrict__ ow,
    const float* __restrict__ ob) {
    __shared__ float xt[18][18];
    __shared__ unsigned long long wdup[NOFF * 9];  // (w,w) pairs

    const int tid  = threadIdx.x;
    const int slot = tid & 127;
    const int og   = tid >> 7;        // 0 or 1
    const int lr   = slot >> 4;       // 0..7
    const int lc   = slot & 15;       // 0..15
    const int b    = blockIdx.z;
    const int by   = blockIdx.y;
    const int bx   = blockIdx.x;

    unsigned long long accp[14];
#pragma unroll
    for (int j = 0; j < 14; ++j) accp[j] = 0ull;

    for (int ci = 0; ci < NC; ++ci) {
        __syncthreads();
        // load 18x18 halo tile for this channel
        for (int i = tid; i < 324; i += 256) {
            int r = i / 18, c = i % 18;
            int gy = by * 16 + r - 1;
            int gx = bx * 16 + c - 1;
            float v = 0.0f;
            if (gy >= 0 && gy < NH && gx >= 0 && gx < NW)
                v = x[((size_t)(b * NC + ci) << 12) + (gy << 6) + gx];
            xt[r][c] = v;
        }
        // load 27x9 weights for this input channel, duplicated
        if (tid < 243) {
            int o = tid / 9, t = tid % 9;
            float wv = ow[((size_t)o * NC + ci) * 9 + t];
            wdup[tid] = pack2(wv, wv);
        }
        __syncthreads();

        unsigned long long xp[9];
#pragma unroll
        for (int dy = 0; dy < 3; ++dy)
#pragma unroll
            for (int dx = 0; dx < 3; ++dx)
                xp[dy * 3 + dx] =
                    pack2(xt[lr + dy][lc + dx], xt[lr + 8 + dy][lc + dx]);

#pragma unroll
        for (int j = 0; j < 14; ++j) {
            int o = og * 14 + j;
            if (o < NOFF) {
#pragma unroll
                for (int t = 0; t < 9; ++t)
                    ffma2(accp[j], xp[t], wdup[o * 9 + t]);
            }
        }
    }

    const int gy0 = by * 16 + lr;
    const int gx  = bx * 16 + lc;
#pragma unroll
    for (int j = 0; j < 14; ++j) {
        int o = og * 14 + j;
        if (o < NOFF) {
            float bb = ob[o];
            float2 a = unpack2(accp[j]);
            g_om[((size_t)(b * NOFF + o) << 12) + (gy0 << 6) + gx]       = a.x + bb;
            g_om[((size_t)(b * NOFF + o) << 12) + ((gy0 + 8) << 6) + gx] = a.y + bb;
        }
    }
}

// ---------------------------------------------------------------------------
// Kernel B: fused deformable sampling + implicit GEMM + BN partial stats.
// Block = 128 consecutive pixels x all 128 out ch; 8px x 8och register tile
// per thread, accumulated as 32 packed f32x2 FFMA2 ops per K element.
// ---------------------------------------------------------------------------
__global__ __launch_bounds__(256, 2) void dcn_main_kernel(
    const float* __restrict__ x,
    const float* __restrict__ bias) {
    __shared__ float s_w00[NKT][128];
    __shared__ float s_w01[NKT][128];
    __shared__ float s_w10[NKT][128];
    __shared__ float s_w11[NKT][128];
    __shared__ unsigned s_cc[NKT][128];
    __shared__ float s_A[16][128];
    __shared__ float s_W[16][128];
    __shared__ float s_sum[NC];
    __shared__ float s_ssq[NC];

    const int tid     = threadIdx.x;
    const int m0      = blockIdx.x * 128;
    const int b       = m0 >> 12;
    const int rowbase = m0 & 4095;
    const int h0      = rowbase >> 6;

    if (tid < NC) { s_sum[tid] = 0.0f; s_ssq[tid] = 0.0f; }

    // -------- phase 1: sampling metadata --------
    for (int idx = tid; idx < NKT * 128; idx += 256) {
        int kt = idx >> 7;
        int px = idx & 127;
        int h  = h0 + (px >> 6);
        int w  = px & 63;
        const float* omb = g_om + (size_t)b * NOFF * NHW;
        float offy = omb[(2 * kt) * NHW + (h << 6) + w];
        float offx = omb[(2 * kt + 1) * NHW + (h << 6) + w];
        float mv   = omb[(18 + kt) * NHW + (h << 6) + w];
        float msk  = 1.0f / (1.0f + expf(-mv));

        float py  = offy + (float)(h - 1 + kt / 3);
        float pxf = offx + (float)(w - 1 + kt % 3);
        float fy = floorf(py), fx = floorf(pxf);
        float ly = py - fy,    lx = pxf - fx;
        int y0 = (int)fy, x0 = (int)fx;
        int y1 = y0 + 1,  x1 = x0 + 1;
        float vy0 = (y0 >= 0 && y0 < NH) ? 1.0f : 0.0f;
        float vy1 = (y1 >= 0 && y1 < NH) ? 1.0f : 0.0f;
        float vx0 = (x0 >= 0 && x0 < NW) ? 1.0f : 0.0f;
        float vx1 = (x1 >= 0 && x1 < NW) ? 1.0f : 0.0f;

        s_w00[kt][px] = (1.0f - ly) * (1.0f - lx) * msk * vy0 * vx0;
        s_w01[kt][px] = (1.0f - ly) * lx          * msk * vy0 * vx1;
        s_w10[kt][px] = ly          * (1.0f - lx) * msk * vy1 * vx0;
        s_w11[kt][px] = ly          * lx          * msk * vy1 * vx1;

        int y0c = min(max(y0, 0), NH - 1), x0c = min(max(x0, 0), NW - 1);
        int y1c = min(max(y1, 0), NH - 1), x1c = min(max(x1, 0), NW - 1);
        s_cc[kt][px] =
            (unsigned)(y0c | (x0c << 6) | (y1c << 12) | (x1c << 18));
    }

    unsigned long long acc2[32];  // [8 px][4 o-pairs]
#pragma unroll
    for (int i = 0; i < 32; ++i) acc2[i] = 0ull;

    const int p0 = (tid >> 4) << 3;  // pixel sub-tile base
    const int o0 = (tid & 15) << 3;  // out-channel sub-tile base

    // -------- phase 2: K loop (channel-block outer, tap inner) --------
    for (int cb = 0; cb < 8; ++cb) {
        const int c0 = cb << 4;
        for (int kt = 0; kt < NKT; ++kt) {
            __syncthreads();  // previous GEMM done reading s_A/s_W
            // load weight tile [16c][128o] (coalesced)
#pragma unroll
            for (int r = 0; r < 8; ++r) {
                int e  = tid + (r << 8);
                int ci = e >> 7;
                int o  = e & 127;
                s_W[ci][o] = g_wT[((kt << 7) + c0 + ci) * NC + o];
            }
            // compute A tile [16c][128px] by bilinear gather
#pragma unroll
            for (int r = 0; r < 8; ++r) {
                int e  = tid + (r << 8);
                int ci = e >> 7;
                int px = e & 127;
                const float* bp = x + ((size_t)(b * NC + c0 + ci) << 12);
                unsigned cc = s_cc[kt][px];
                int y0c = cc & 63;
                int x0c = (cc >> 6) & 63;
                int y1c = (cc >> 12) & 63;
                int x1c = (cc >> 18) & 63;
                float a = s_w00[kt][px] * __ldg(bp + (y0c << 6) + x0c)
                        + s_w01[kt][px] * __ldg(bp + (y0c << 6) + x1c)
                        + s_w10[kt][px] * __ldg(bp + (y1c << 6) + x0c)
                        + s_w11[kt][px] * __ldg(bp + (y1c << 6) + x1c);
                s_A[ci][px] = a;
            }
            __syncthreads();
            // 8x8 register-tile GEMM update via FFMA2
#pragma unroll
            for (int ci = 0; ci < 16; ++ci) {
                float4 a0 = *(const float4*)(&s_A[ci][p0]);
                float4 a1 = *(const float4*)(&s_A[ci][p0 + 4]);
                ulonglong2 wA = *(const ulonglong2*)(&s_W[ci][o0]);
                ulonglong2 wB = *(const ulonglong2*)(&s_W[ci][o0 + 4]);
                float av[8] = {a0.x, a0.y, a0.z, a0.w, a1.x, a1.y, a1.z, a1.w};
#pragma unroll
                for (int i = 0; i < 8; ++i) {
                    unsigned long long ab = bcast2(av[i]);
                    ffma2(acc2[i * 4 + 0], ab, wA.x);
                    ffma2(acc2[i * 4 + 1], ab, wA.y);
                    ffma2(acc2[i * 4 + 2], ab, wB.x);
                    ffma2(acc2[i * 4 + 3], ab, wB.y);
                }
            }
        }
    }

    // unpack packed accumulators: acc2[i*4+j2] lo -> o0+2*j2, hi -> o0+2*j2+1
    float accf[64];
#pragma unroll
    for (int i = 0; i < 8; ++i)
#pragma unroll
        for (int j2 = 0; j2 < 4; ++j2) {
            float2 t = unpack2(acc2[i * 4 + j2]);
            accf[i * 8 + 2 * j2]     = t.x;
            accf[i * 8 + 2 * j2 + 1] = t.y;
        }

    // -------- epilogue: bias, store y, BN partial stats --------
#pragma unroll
    for (int j = 0; j < 8; ++j) {
        int o = o0 + j;
        float bo = __ldg(bias + o);
        float v[8];
        float s = 0.0f, sq = 0.0f;
#pragma unroll
        for (int i = 0; i < 8; ++i) {
            v[i] = accf[i * 8 + j] + bo;
            s += v[i];
            sq = fmaf(v[i], v[i], sq);
        }
        float* yp = g_y + ((size_t)(b * NC + o) << 12) + rowbase + p0;
        *(float4*)yp       = make_float4(v[0], v[1], v[2], v[3]);
        *(float4*)(yp + 4) = make_float4(v[4], v[5], v[6], v[7]);
        atomicAdd(&s_sum[o], s);
        atomicAdd(&s_ssq[o], sq);
    }
    __syncthreads();
    if (tid < NC) {
        atomicAdd(&g_stats[tid], s_sum[tid]);
        atomicAdd(&g_stats[NC + tid], s_ssq[tid]);
    }
}

// ---------------------------------------------------------------------------
// Kernel D: BatchNorm (batch stats) + ReLU -> d_out
// ---------------------------------------------------------------------------
__global__ __launch_bounds__(256) void bn_relu_kernel(
    float* __restrict__ out,
    const float* __restrict__ gamma,
    const float* __restrict__ beta) {
    int idx = blockIdx.x * 256 + threadIdx.x;  // float4 index, total 1048576
    int o = (idx >> 10) & 127;                 // 1024 float4 per (b,o) plane
    const float invN = 1.0f / 32768.0f;
    float mean = g_stats[o] * invN;
    float var  = g_stats[NC + o] * invN - mean * mean;
    float inv  = rsqrtf(var + 1e-5f);
    float sc   = gamma[o] * inv;
    float sh   = beta[o] - mean * sc;
    float4 v = ((const float4*)g_y)[idx];
    v.x = fmaxf(fmaf(v.x, sc, sh), 0.0f);
    v.y = fmaxf(fmaf(v.y, sc, sh), 0.0f);
    v.z = fmaxf(fmaf(v.z, sc, sh), 0.0f);
    v.w = fmaxf(fmaf(v.w, sc, sh), 0.0f);
    ((float4*)out)[idx] = v;
}

// ---------------------------------------------------------------------------
extern "C" void kernel_launch(void* const* d_in, const int* in_sizes, int n_in,
                              void* d_out, int out_size) {
    const float* x     = (const float*)d_in[0];
    const float* off_w = (const float*)d_in[1];
    const float* off_b = (const float*)d_in[2];
    const float* w     = (const float*)d_in[3];
    const float* bias  = (const float*)d_in[4];
    const float* gamma = (const float*)d_in[5];
    const float* beta  = (const float*)d_in[6];
    float* out = (float*)d_out;

    prep_kernel<<<144, 256>>>(w);
    off_conv_kernel<<<dim3(4, 4, 8), 256>>>(x, off_w, off_b);
    dcn_main_kernel<<<256, 256>>>(x, bias);
    bn_relu_kernel<<<4096, 256>>>(out, gamma, beta);
}

// round 6
// speedup vs baseline: 1.4214x; 1.4214x over previous
#include <cuda_runtime.h>
#include <cuda_bf16.h>
#include <math.h>
#include <stdint.h>

// Shapes: x[8,128,64,64] off_w[27,128,3,3] off_b[27] w[128,128,3,3] b[128]
//         gamma[128] beta[128] -> out[8,128,64,64] fp32

#define NB   8
#define NC   128
#define NH   64
#define NW   64
#define NHW  4096
#define NKT  9
#define NOFF 27
#define KDIM 1152   // 128*9

static __device__ float g_om[NB * NOFF * NHW];   // offset-conv output
static __device__ float g_y[NB * NC * NHW];      // pre-BN conv output
static __device__ float g_stats[2 * NC];         // per-channel sum, sumsq

// ---------------- helpers ---------------------------------------------------
__device__ __forceinline__ uint32_t f2tf32(float v) {
    uint32_t r;
    asm("cvt.rna.tf32.f32 %0, %1;" : "=r"(r) : "f"(v));
    return r;
}
// D += A(16x8 row) * B(8x8 col)  tf32, fp32 accum
__device__ __forceinline__ void mma_tf32(float4& d, const uint32_t a[4],
                                         const uint32_t b[2]) {
    asm volatile(
        "mma.sync.aligned.m16n8k8.row.col.f32.tf32.tf32.f32 "
        "{%0,%1,%2,%3}, {%4,%5,%6,%7}, {%8,%9}, {%0,%1,%2,%3};"
        : "+f"(d.x), "+f"(d.y), "+f"(d.z), "+f"(d.w)
        : "r"(a[0]), "r"(a[1]), "r"(a[2]), "r"(a[3]), "r"(b[0]), "r"(b[1]));
}
__device__ __forceinline__ void ffma2(unsigned long long& d,
                                      unsigned long long a,
                                      unsigned long long b) {
    asm volatile("fma.rn.f32x2 %0, %1, %2, %0;" : "+l"(d) : "l"(a), "l"(b));
}
__device__ __forceinline__ unsigned long long pack2(float lo, float hi) {
    unsigned long long r;
    asm("mov.b64 %0, {%1, %2};" : "=l"(r) : "f"(lo), "f"(hi));
    return r;
}
__device__ __forceinline__ float2 unpack2(unsigned long long v) {
    float2 r;
    asm("mov.b64 {%0, %1}, %2;" : "=f"(r.x), "=f"(r.y) : "l"(v));
    return r;
}

// SMEM layout (dynamic, byte offsets). A/W tiles stride 36 floats (144B).
#define OFF_SUM  0        // 512
#define OFF_SSQ  512      // 512
#define OFF_BIAS 1024     // 512
#define OFF_CC   1536     // 9*128*4  = 4608
#define OFF_WQ   6144     // 9*128*16 = 18432
#define OFF_A    24576    // 128*36*4 = 18432
#define OFF_W    43008    // 128*36*4 = 18432
#define SMEM_SZ  61440
#define TSTRIDE  36       // floats; 36 mod 32 = 4 -> conflict-free frag LDS

// ---------------------------------------------------------------------------
// Kernel Z: zero BN stats
// ---------------------------------------------------------------------------
__global__ void prep_kernel() {
    if (threadIdx.x < 2 * NC) g_stats[threadIdx.x] = 0.0f;
}

// ---------------------------------------------------------------------------
// Kernel A: offset conv (FFMA2 pixel-pair version)
// ---------------------------------------------------------------------------
__global__ __launch_bounds__(256) void off_conv_kernel(
    const float* __restrict__ x,
    const float* __restrict__ ow,
    const float* __restrict__ ob) {
    __shared__ float xt[18][18];
    __shared__ unsigned long long wdup[NOFF * 9];

    const int tid  = threadIdx.x;
    const int slot = tid & 127;
    const int og   = tid >> 7;
    const int lr   = slot >> 4;
    const int lc   = slot & 15;
    const int b    = blockIdx.z;
    const int by   = blockIdx.y;
    const int bx   = blockIdx.x;

    unsigned long long accp[14];
#pragma unroll
    for (int j = 0; j < 14; ++j) accp[j] = 0ull;

    for (int ci = 0; ci < NC; ++ci) {
        __syncthreads();
        for (int i = tid; i < 324; i += 256) {
            int r = i / 18, c = i % 18;
            int gy = by * 16 + r - 1;
            int gx = bx * 16 + c - 1;
            float v = 0.0f;
            if (gy >= 0 && gy < NH && gx >= 0 && gx < NW)
                v = x[((size_t)(b * NC + ci) << 12) + (gy << 6) + gx];
            xt[r][c] = v;
        }
        if (tid < 243) {
            int o = tid / 9, t = tid % 9;
            float wv = ow[((size_t)o * NC + ci) * 9 + t];
            wdup[tid] = pack2(wv, wv);
        }
        __syncthreads();

        unsigned long long xp[9];
#pragma unroll
        for (int dy = 0; dy < 3; ++dy)
#pragma unroll
            for (int dx = 0; dx < 3; ++dx)
                xp[dy * 3 + dx] =
                    pack2(xt[lr + dy][lc + dx], xt[lr + 8 + dy][lc + dx]);

#pragma unroll
        for (int j = 0; j < 14; ++j) {
            int o = og * 14 + j;
            if (o < NOFF) {
#pragma unroll
                for (int t = 0; t < 9; ++t)
                    ffma2(accp[j], xp[t], wdup[o * 9 + t]);
            }
        }
    }

    const int gy0 = by * 16 + lr;
    const int gx  = bx * 16 + lc;
#pragma unroll
    for (int j = 0; j < 14; ++j) {
        int o = og * 14 + j;
        if (o < NOFF) {
            float bb = ob[o];
            float2 a = unpack2(accp[j]);
            g_om[((size_t)(b * NOFF + o) << 12) + (gy0 << 6) + gx]       = a.x + bb;
            g_om[((size_t)(b * NOFF + o) << 12) + ((gy0 + 8) << 6) + gx] = a.y + bb;
        }
    }
}

// ---------------------------------------------------------------------------
// Kernel B: deformable sampling + mma.sync tf32 implicit GEMM + BN stats.
// Block = 128 px x 128 o; 8 warps in 2x4 grid, warp tile 64px x 32o.
// K = 1152, 36 chunks of 32; m16n8k8 fragments loaded from stride-36 SMEM.
// ---------------------------------------------------------------------------
__global__ __launch_bounds__(256) void dcn_main_kernel(
    const float* __restrict__ x,
    const float* __restrict__ wsrc,
    const float* __restrict__ bias) {
    extern __shared__ char smem[];
    const int tid  = threadIdx.x;
    const int wid  = tid >> 5;
    const int lane = tid & 31;
    const int wr   = wid >> 2;   // 0..1  (M half)
    const int wc   = wid & 3;    // 0..3  (N quarter)
    const int fr   = lane >> 2;  // fragment row group 0..7
    const int fc   = lane & 3;   // fragment col group 0..3

    const int m0      = blockIdx.x * 128;
    const int b       = m0 >> 12;
    const int rowbase = m0 & 4095;
    const int h0      = rowbase >> 6;

    float*    s_sum = (float*)(smem + OFF_SUM);
    float*    s_ssq = (float*)(smem + OFF_SSQ);
    float*    s_bias = (float*)(smem + OFF_BIAS);
    unsigned* s_cc = (unsigned*)(smem + OFF_CC);
    float4*   s_wq = (float4*)(smem + OFF_WQ);
    uint32_t* s_A  = (uint32_t*)(smem + OFF_A);
    uint32_t* s_W  = (uint32_t*)(smem + OFF_W);

    if (tid < NC) {
        s_sum[tid] = 0.0f;
        s_ssq[tid] = 0.0f;
        s_bias[tid] = bias[tid];
    }

    // -------- phase 1: sampling metadata --------
    for (int idx = tid; idx < NKT * 128; idx += 256) {
        int kt = idx >> 7;
        int px = idx & 127;
        int h  = h0 + (px >> 6);
        int w  = px & 63;
        const float* omb = g_om + (size_t)b * NOFF * NHW;
        float offy = omb[(2 * kt) * NHW + (h << 6) + w];
        float offx = omb[(2 * kt + 1) * NHW + (h << 6) + w];
        float mv   = omb[(18 + kt) * NHW + (h << 6) + w];
        float msk  = 1.0f / (1.0f + expf(-mv));

        float py  = offy + (float)(h - 1 + kt / 3);
        float pxf = offx + (float)(w - 1 + kt % 3);
        float fy = floorf(py), fx = floorf(pxf);
        float ly = py - fy,    lx = pxf - fx;
        int y0 = (int)fy, x0 = (int)fx;
        int y1 = y0 + 1,  x1 = x0 + 1;
        float vy0 = (y0 >= 0 && y0 < NH) ? 1.0f : 0.0f;
        float vy1 = (y1 >= 0 && y1 < NH) ? 1.0f : 0.0f;
        float vx0 = (x0 >= 0 && x0 < NW) ? 1.0f : 0.0f;
        float vx1 = (x1 >= 0 && x1 < NW) ? 1.0f : 0.0f;

        float4 wq;
        wq.x = (1.0f - ly) * (1.0f - lx) * msk * vy0 * vx0;
        wq.y = (1.0f - ly) * lx          * msk * vy0 * vx1;
        wq.z = ly          * (1.0f - lx) * msk * vy1 * vx0;
        wq.w = ly          * lx          * msk * vy1 * vx1;
        s_wq[idx] = wq;

        int y0c = min(max(y0, 0), NH - 1), x0c = min(max(x0, 0), NW - 1);
        int y1c = min(max(y1, 0), NH - 1), x1c = min(max(x1, 0), NW - 1);
        s_cc[idx] = (unsigned)(y0c | (x0c << 6) | (y1c << 12) | (x1c << 18));
    }

    float4 acc[4][4];
#pragma unroll
    for (int i = 0; i < 4; ++i)
#pragma unroll
        for (int j = 0; j < 4; ++j)
            acc[i][j] = make_float4(0.f, 0.f, 0.f, 0.f);

    const int half = tid >> 7;   // which 16-k half of the chunk this thread fills
    const int px   = tid & 127;

    // -------- phase 2: 36 K-chunks of 32 --------
    for (int c = 0; c < 36; ++c) {
        __syncthreads();  // previous compute done reading tiles / phase-1 ready

        // ---- fill A tile: thread -> (px, 16 k's as 4 quads), tf32 bits ----
#pragma unroll
        for (int q = 0; q < 4; ++q) {
            int kk0 = half * 16 + q * 4;
            uint32_t pk[4];
#pragma unroll
            for (int j = 0; j < 4; ++j) {
                int k  = c * 32 + kk0 + j;
                int ci = k / 9;
                int kt = k - ci * 9;
                const float* bp = x + ((size_t)((b << 7) + ci) << 12);
                float4   wq = s_wq[(kt << 7) + px];
                unsigned cc = s_cc[(kt << 7) + px];
                int y0c = cc & 63, x0c = (cc >> 6) & 63;
                int y1c = (cc >> 12) & 63, x1c = (cc >> 18) & 63;
                float a = wq.x * __ldg(bp + (y0c << 6) + x0c)
                        + wq.y * __ldg(bp + (y0c << 6) + x1c)
                        + wq.z * __ldg(bp + (y1c << 6) + x0c)
                        + wq.w * __ldg(bp + (y1c << 6) + x1c);
                pk[j] = f2tf32(a);
            }
            *(uint4*)(s_A + px * TSTRIDE + kk0) =
                make_uint4(pk[0], pk[1], pk[2], pk[3]);
        }
        // ---- fill W tile: warp wid -> o rows [wid*16, wid*16+16), lane = k --
        {
            const float* wrow = wsrc + c * 32 + lane;
#pragma unroll
            for (int r2 = 0; r2 < 16; ++r2) {
                int o = wid * 16 + r2;
                s_W[o * TSTRIDE + lane] = f2tf32(__ldg(wrow + o * KDIM));
            }
        }
        __syncthreads();

        // ---- warp GEMM: 4 k-steps of 8 ----
#pragma unroll
        for (int ks = 0; ks < 4; ++ks) {
            const int kb = ks * 8;
            uint32_t bfr[4][2];
#pragma unroll
            for (int j = 0; j < 4; ++j) {
                const uint32_t* wp =
                    s_W + (wc * 32 + j * 8 + fr) * TSTRIDE + kb + fc;
                bfr[j][0] = wp[0];
                bfr[j][1] = wp[4];
            }
#pragma unroll
            for (int i = 0; i < 4; ++i) {
                uint32_t afr[4];
                const uint32_t* ap =
                    s_A + (wr * 64 + i * 16 + fr) * TSTRIDE + kb + fc;
                afr[0] = ap[0];
                afr[1] = ap[8 * TSTRIDE];
                afr[2] = ap[4];
                afr[3] = ap[8 * TSTRIDE + 4];
#pragma unroll
                for (int j = 0; j < 4; ++j)
                    mma_tf32(acc[i][j], afr, bfr[j]);
            }
        }
    }
    __syncthreads();

    // -------- epilogue: bias, store y, BN partial stats --------
#pragma unroll
    for (int j = 0; j < 4; ++j) {
#pragma unroll
        for (int t = 0; t < 2; ++t) {
            int o = wc * 32 + j * 8 + 2 * fc + t;
            float bo = s_bias[o];
            float* yp = g_y + (((size_t)((b << 7) + o)) << 12) + rowbase;
            float s = 0.0f, q = 0.0f;
#pragma unroll
            for (int i = 0; i < 4; ++i) {
                float v1 = (t ? acc[i][j].y : acc[i][j].x) + bo;
                float v2 = (t ? acc[i][j].w : acc[i][j].z) + bo;
                int p1 = wr * 64 + i * 16 + fr;
                yp[p1]     = v1;
                yp[p1 + 8] = v2;
                s += v1 + v2;
                q += v1 * v1 + v2 * v2;
            }
            atomicAdd(&s_sum[o], s);
            atomicAdd(&s_ssq[o], q);
        }
    }
    __syncthreads();
    if (tid < NC) {
        atomicAdd(&g_stats[tid],      s_sum[tid]);
        atomicAdd(&g_stats[NC + tid], s_ssq[tid]);
    }
}

// ---------------------------------------------------------------------------
// Kernel D: BatchNorm (batch stats) + ReLU -> d_out
// ---------------------------------------------------------------------------
__global__ __launch_bounds__(256) void bn_relu_kernel(
    float* __restrict__ out,
    const float* __restrict__ gamma,
    const float* __restrict__ beta) {
    int idx = blockIdx.x * 256 + threadIdx.x;
    int o = (idx >> 10) & 127;
    const float invN = 1.0f / 32768.0f;
    float mean = g_stats[o] * invN;
    float var  = g_stats[NC + o] * invN - mean * mean;
    float inv  = rsqrtf(var + 1e-5f);
    float sc   = gamma[o] * inv;
    float sh   = beta[o] - mean * sc;
    float4 v = ((const float4*)g_y)[idx];
    v.x = fmaxf(fmaf(v.x, sc, sh), 0.0f);
    v.y = fmaxf(fmaf(v.y, sc, sh), 0.0f);
    v.z = fmaxf(fmaf(v.z, sc, sh), 0.0f);
    v.w = fmaxf(fmaf(v.w, sc, sh), 0.0f);
    ((float4*)out)[idx] = v;
}

// ---------------------------------------------------------------------------
extern "C" void kernel_launch(void* const* d_in, const int* in_sizes, int n_in,
                              void* d_out, int out_size) {
    const float* x     = (const float*)d_in[0];
    const float* off_w = (const float*)d_in[1];
    const float* off_b = (const float*)d_in[2];
    const float* w     = (const float*)d_in[3];
    const float* bias  = (const float*)d_in[4];
    const float* gamma = (const float*)d_in[5];
    const float* beta  = (const float*)d_in[6];
    float* out = (float*)d_out;

    cudaFuncSetAttribute(dcn_main_kernel,
                         cudaFuncAttributeMaxDynamicSharedMemorySize, SMEM_SZ);

    prep_kernel<<<1, 256>>>();
    off_conv_kernel<<<dim3(4, 4, 8), 256>>>(x, off_w, off_b);
    dcn_main_kernel<<<256, 256, SMEM_SZ>>>(x, w, bias);
    bn_relu_kernel<<<4096, 256>>>(out, gamma, beta);
}

// round 7
// speedup vs baseline: 1.4582x; 1.0259x over previous
#include <cuda_runtime.h>
#include <cuda_bf16.h>
#include <math.h>
#include <stdint.h>

// Shapes: x[8,128,64,64] off_w[27,128,3,3] off_b[27] w[128,128,3,3] b[128]
//         gamma[128] beta[128] -> out[8,128,64,64] fp32

#define NB   8
#define NC   128
#define NH   64
#define NW   64
#define NHW  4096
#define NKT  9
#define NOFF 27
#define KDIM 1152   // 128*9

static __device__ float g_om[NB * NOFF * NHW];   // offset-conv output
static __device__ float g_w2[NC * KDIM];         // w permuted: [o][kt*128+ci]
static __device__ float g_y[NB * NC * NHW];      // pre-BN conv output
static __device__ float g_stats[2 * NC];         // per-channel sum, sumsq

// ---------------- helpers ---------------------------------------------------
__device__ __forceinline__ uint32_t f2tf32(float v) {
    uint32_t r;
    asm("cvt.rna.tf32.f32 %0, %1;" : "=r"(r) : "f"(v));
    return r;
}
__device__ __forceinline__ void mma_tf32(float4& d, const uint32_t a[4],
                                         const uint32_t b[2]) {
    asm volatile(
        "mma.sync.aligned.m16n8k8.row.col.f32.tf32.tf32.f32 "
        "{%0,%1,%2,%3}, {%4,%5,%6,%7}, {%8,%9}, {%0,%1,%2,%3};"
        : "+f"(d.x), "+f"(d.y), "+f"(d.z), "+f"(d.w)
        : "r"(a[0]), "r"(a[1]), "r"(a[2]), "r"(a[3]), "r"(b[0]), "r"(b[1]));
}
__device__ __forceinline__ void ffma2(unsigned long long& d,
                                      unsigned long long a,
                                      unsigned long long b) {
    asm volatile("fma.rn.f32x2 %0, %1, %2, %0;" : "+l"(d) : "l"(a), "l"(b));
}
__device__ __forceinline__ unsigned long long pack2(float lo, float hi) {
    unsigned long long r;
    asm("mov.b64 %0, {%1, %2};" : "=l"(r) : "f"(lo), "f"(hi));
    return r;
}
__device__ __forceinline__ float2 unpack2(unsigned long long v) {
    float2 r;
    asm("mov.b64 {%0, %1}, %2;" : "=f"(r.x), "=f"(r.y) : "l"(v));
    return r;
}

// SMEM layout (dynamic, byte offsets). Tiles stride 36 floats (conflict-free).
#define OFF_SUM  0         // 512
#define OFF_SSQ  512       // 512
#define OFF_BIAS 1024      // 512
#define OFF_CO   1536      // 9*128*8  = 9216  (ushort4 corner byte-offsets)
#define OFF_WQ   10752     // 9*128*16 = 18432 (float4 bilinear weights)
#define OFF_A0   29184     // 128*36*4 = 18432
#define OFF_A1   47616
#define OFF_W0   66048
#define OFF_W1   84480
#define SMEM_SZ  102912
#define TSTRIDE  36

// ---------------------------------------------------------------------------
// Kernel Z: zero stats + permute weights to [o][kt*128+ci]
// ---------------------------------------------------------------------------
__global__ void prep_kernel(const float* __restrict__ w) {
    if (blockIdx.x == 0 && threadIdx.x < 2 * NC) g_stats[threadIdx.x] = 0.0f;
    int n = NC * KDIM;
    for (int i = blockIdx.x * blockDim.x + threadIdx.x; i < n;
         i += gridDim.x * blockDim.x) {
        int o  = i / KDIM;
        int r  = i - o * KDIM;
        int kt = r >> 7;
        int ci = r & 127;
        g_w2[i] = w[o * KDIM + ci * 9 + kt];
    }
}

// ---------------------------------------------------------------------------
// Kernel A: offset conv. 256 blocks (8h x 16w tiles), 4 channels / iteration.
// slot = tid&63 -> (lr 0..3 pairs rows lr/lr+4, lc 0..15); og = tid>>6 -> 7
// outputs each (last group 6). FFMA2 over pixel pairs.
// ---------------------------------------------------------------------------
__global__ __launch_bounds__(256) void off_conv_kernel(
    const float* __restrict__ x,
    const float* __restrict__ ow,
    const float* __restrict__ ob) {
    __shared__ float xt[4][10][18];
    __shared__ unsigned long long wdup[4 * 243];

    const int tid  = threadIdx.x;
    const int og   = tid >> 6;        // 0..3
    const int slot = tid & 63;
    const int lr   = slot >> 4;       // 0..3
    const int lc   = slot & 15;
    const int b    = blockIdx.z;
    const int by   = blockIdx.y;      // 0..7 (8-row tiles)
    const int bx   = blockIdx.x;      // 0..3 (16-col tiles)

    unsigned long long accp[7];
#pragma unroll
    for (int j = 0; j < 7; ++j) accp[j] = 0ull;

    for (int it = 0; it < 32; ++it) {
        const int ci0 = it << 2;
        __syncthreads();
        // halo tiles for 4 channels: 4 x 10 x 18
        for (int i = tid; i < 720; i += 256) {
            int ci  = i / 180;
            int rem = i - ci * 180;
            int r   = rem / 18;
            int cp  = rem - r * 18;
            int gy  = by * 8 + r - 1;
            int gx  = bx * 16 + cp - 1;
            float v = 0.0f;
            if (gy >= 0 && gy < NH && gx >= 0 && gx < NW)
                v = __ldg(x + ((size_t)(b * NC + ci0 + ci) << 12) + (gy << 6) + gx);
            xt[ci][r][cp] = v;
        }
        // weights for 4 channels, duplicated pairs
        for (int i = tid; i < 972; i += 256) {
            int ci  = i / 243;
            int rem = i - ci * 243;
            int o   = rem / 9;
            int t   = rem - o * 9;
            float wv = __ldg(ow + (size_t)o * KDIM + (ci0 + ci) * 9 + t);
            wdup[i] = pack2(wv, wv);
        }
        __syncthreads();

#pragma unroll
        for (int ci = 0; ci < 4; ++ci) {
            unsigned long long xp[9];
#pragma unroll
            for (int dy = 0; dy < 3; ++dy)
#pragma unroll
                for (int dx = 0; dx < 3; ++dx)
                    xp[dy * 3 + dx] = pack2(xt[ci][lr + dy][lc + dx],
                                            xt[ci][lr + 4 + dy][lc + dx]);
#pragma unroll
            for (int j = 0; j < 7; ++j) {
                int o = og * 7 + j;
                if (o < NOFF) {
#pragma unroll
                    for (int t = 0; t < 9; ++t)
                        ffma2(accp[j], xp[t], wdup[ci * 243 + o * 9 + t]);
                }
            }
        }
    }

    const int gy0 = by * 8 + lr;
    const int gx  = bx * 16 + lc;
#pragma unroll
    for (int j = 0; j < 7; ++j) {
        int o = og * 7 + j;
        if (o < NOFF) {
            float bb = __ldg(ob + o);
            float2 a = unpack2(accp[j]);
            g_om[((size_t)(b * NOFF + o) << 12) + (gy0 << 6) + gx]       = a.x + bb;
            g_om[((size_t)(b * NOFF + o) << 12) + ((gy0 + 4) << 6) + gx] = a.y + bb;
        }
    }
}

// ---------------------------------------------------------------------------
// Kernel B: deformable sampling + mma.sync tf32 implicit GEMM + BN stats.
// K ordered kt-major (k' = kt*128 + ci): chunk c -> tap kt=c>>2, ci0=(c&3)*32.
// Per-thread A-fill: coords/weights loaded once per chunk, 16 channels via
// LDG [reg+imm]. Double-buffered tiles, 1 sync per chunk.
// ---------------------------------------------------------------------------
__global__ __launch_bounds__(256) void dcn_main_kernel(
    const float* __restrict__ x,
    const float* __restrict__ bias) {
    extern __shared__ char smem[];
    const int tid  = threadIdx.x;
    const int wid  = tid >> 5;
    const int lane = tid & 31;
    const int wr   = wid >> 2;   // 0..1  (M half)
    const int wc   = wid & 3;    // 0..3  (N quarter)
    const int fr   = lane >> 2;
    const int fc   = lane & 3;

    const int m0      = blockIdx.x * 128;
    const int b       = m0 >> 12;
    const int rowbase = m0 & 4095;
    const int h0      = rowbase >> 6;

    float*   s_sum  = (float*)(smem + OFF_SUM);
    float*   s_ssq  = (float*)(smem + OFF_SSQ);
    float*   s_bias = (float*)(smem + OFF_BIAS);
    ushort4* s_co   = (ushort4*)(smem + OFF_CO);
    float4*  s_wq   = (float4*)(smem + OFF_WQ);
    uint32_t* s_Ab[2] = {(uint32_t*)(smem + OFF_A0), (uint32_t*)(smem + OFF_A1)};
    uint32_t* s_Wb[2] = {(uint32_t*)(smem + OFF_W0), (uint32_t*)(smem + OFF_W1)};

    if (tid < NC) {
        s_sum[tid] = 0.0f;
        s_ssq[tid] = 0.0f;
        s_bias[tid] = bias[tid];
    }

    // -------- phase 1: sampling metadata --------
    for (int idx = tid; idx < NKT * 128; idx += 256) {
        int kt = idx >> 7;
        int px = idx & 127;
        int h  = h0 + (px >> 6);
        int w  = px & 63;
        const float* omb = g_om + (size_t)b * NOFF * NHW;
        float offy = omb[(2 * kt) * NHW + (h << 6) + w];
        float offx = omb[(2 * kt + 1) * NHW + (h << 6) + w];
        float mv   = omb[(18 + kt) * NHW + (h << 6) + w];
        float msk  = 1.0f / (1.0f + expf(-mv));

        float py  = offy + (float)(h - 1 + kt / 3);
        float pxf = offx + (float)(w - 1 + kt % 3);
        float fy = floorf(py), fx = floorf(pxf);
        float ly = py - fy,    lx = pxf - fx;
        int y0 = (int)fy, x0 = (int)fx;
        int y1 = y0 + 1,  x1 = x0 + 1;
        float vy0 = (y0 >= 0 && y0 < NH) ? 1.0f : 0.0f;
        float vy1 = (y1 >= 0 && y1 < NH) ? 1.0f : 0.0f;
        float vx0 = (x0 >= 0 && x0 < NW) ? 1.0f : 0.0f;
        float vx1 = (x1 >= 0 && x1 < NW) ? 1.0f : 0.0f;

        float4 wq;
        wq.x = (1.0f - ly) * (1.0f - lx) * msk * vy0 * vx0;
        wq.y = (1.0f - ly) * lx          * msk * vy0 * vx1;
        wq.z = ly          * (1.0f - lx) * msk * vy1 * vx0;
        wq.w = ly          * lx          * msk * vy1 * vx1;
        s_wq[idx] = wq;

        int y0c = min(max(y0, 0), NH - 1), x0c = min(max(x0, 0), NW - 1);
        int y1c = min(max(y1, 0), NH - 1), x1c = min(max(x1, 0), NW - 1);
        ushort4 co;
        co.x = (unsigned short)(((y0c << 6) + x0c) << 2);
        co.y = (unsigned short)(((y0c << 6) + x1c) << 2);
        co.z = (unsigned short)(((y1c << 6) + x0c) << 2);
        co.w = (unsigned short)(((y1c << 6) + x1c) << 2);
        s_co[idx] = co;
    }

    float4 acc[4][4];
#pragma unroll
    for (int i = 0; i < 4; ++i)
#pragma unroll
        for (int j = 0; j < 4; ++j)
            acc[i][j] = make_float4(0.f, 0.f, 0.f, 0.f);

    const int half = tid >> 7;
    const int px   = tid & 127;

    // ---- tile fill lambdas ----
    auto fillA = [&](uint32_t* sA, int c) {
        const int kt  = c >> 2;
        const int cib = ((c & 3) << 5) + half * 16;
        const int midx = (kt << 7) + px;
        const float4  wq = s_wq[midx];
        const ushort4 co = s_co[midx];
        const char* bpx =
            (const char*)x + (((size_t)((b << 7) + cib)) << 14);
        uint32_t pk[4];
#pragma unroll
        for (int j = 0; j < 16; ++j) {
            const char* p = bpx + j * 16384;
            float v = wq.x * __ldg((const float*)(p + co.x))
                    + wq.y * __ldg((const float*)(p + co.y))
                    + wq.z * __ldg((const float*)(p + co.z))
                    + wq.w * __ldg((const float*)(p + co.w));
            pk[j & 3] = f2tf32(v);
            if ((j & 3) == 3)
                *(uint4*)(sA + px * TSTRIDE + half * 16 + (j - 3)) =
                    make_uint4(pk[0], pk[1], pk[2], pk[3]);
        }
    };
    auto fillW = [&](uint32_t* sW, int c) {
        const float* wrow = g_w2 + c * 32 + lane;
#pragma unroll
        for (int r2 = 0; r2 < 16; ++r2) {
            int o = wid * 16 + r2;
            sW[o * TSTRIDE + lane] = f2tf32(__ldg(wrow + o * KDIM));
        }
    };

    __syncthreads();  // phase-1 metadata ready
    fillA(s_Ab[0], 0);
    fillW(s_Wb[0], 0);
    __syncthreads();

    // -------- phase 2: 36 K-chunks, double-buffered, 1 sync/chunk --------
    for (int c = 0; c < 36; ++c) {
        const int st = c & 1;
        if (c < 35) {               // prefetch next chunk
            fillA(s_Ab[st ^ 1], c + 1);
            fillW(s_Wb[st ^ 1], c + 1);
        }
        const uint32_t* s_A = s_Ab[st];
        const uint32_t* s_W = s_Wb[st];
#pragma unroll
        for (int ks = 0; ks < 4; ++ks) {
            const int kb = ks * 8;
            uint32_t bfr[4][2];
#pragma unroll
            for (int j = 0; j < 4; ++j) {
                const uint32_t* wp =
                    s_W + (wc * 32 + j * 8 + fr) * TSTRIDE + kb + fc;
                bfr[j][0] = wp[0];
                bfr[j][1] = wp[4];
            }
#pragma unroll
            for (int i = 0; i < 4; ++i) {
                uint32_t afr[4];
                const uint32_t* ap =
                    s_A + (wr * 64 + i * 16 + fr) * TSTRIDE + kb + fc;
                afr[0] = ap[0];
                afr[1] = ap[8 * TSTRIDE];
                afr[2] = ap[4];
                afr[3] = ap[8 * TSTRIDE + 4];
#pragma unroll
                for (int j = 0; j < 4; ++j)
                    mma_tf32(acc[i][j], afr, bfr[j]);
            }
        }
        __syncthreads();
    }

    // -------- epilogue: bias, store y, BN partial stats --------
#pragma unroll
    for (int j = 0; j < 4; ++j) {
#pragma unroll
        for (int t = 0; t < 2; ++t) {
            int o = wc * 32 + j * 8 + 2 * fc + t;
            float bo = s_bias[o];
            float* yp = g_y + (((size_t)((b << 7) + o)) << 12) + rowbase;
            float s = 0.0f, q = 0.0f;
#pragma unroll
            for (int i = 0; i < 4; ++i) {
                float v1 = (t ? acc[i][j].y : acc[i][j].x) + bo;
                float v2 = (t ? acc[i][j].w : acc[i][j].z) + bo;
                int p1 = wr * 64 + i * 16 + fr;
                yp[p1]     = v1;
                yp[p1 + 8] = v2;
                s += v1 + v2;
                q += v1 * v1 + v2 * v2;
            }
            atomicAdd(&s_sum[o], s);
            atomicAdd(&s_ssq[o], q);
        }
    }
    __syncthreads();
    if (tid < NC) {
        atomicAdd(&g_stats[tid],      s_sum[tid]);
        atomicAdd(&g_stats[NC + tid], s_ssq[tid]);
    }
}

// ---------------------------------------------------------------------------
// Kernel D: BatchNorm (batch stats) + ReLU -> d_out
// ---------------------------------------------------------------------------
__global__ __launch_bounds__(256) void bn_relu_kernel(
    float* __restrict__ out,
    const float* __restrict__ gamma,
    const float* __restrict__ beta) {
    int idx = blockIdx.x * 256 + threadIdx.x;
    int o = (idx >> 10) & 127;
    const float invN = 1.0f / 32768.0f;
    float mean = g_stats[o] * invN;
    float var  = g_stats[NC + o] * invN - mean * mean;
    float inv  = rsqrtf(var + 1e-5f);
    float sc   = gamma[o] * inv;
    float sh   = beta[o] - mean * sc;
    float4 v = ((const float4*)g_y)[idx];
    v.x = fmaxf(fmaf(v.x, sc, sh), 0.0f);
    v.y = fmaxf(fmaf(v.y, sc, sh), 0.0f);
    v.z = fmaxf(fmaf(v.z, sc, sh), 0.0f);
    v.w = fmaxf(fmaf(v.w, sc, sh), 0.0f);
    ((float4*)out)[idx] = v;
}

// ---------------------------------------------------------------------------
extern "C" void kernel_launch(void* const* d_in, const int* in_sizes, int n_in,
                              void* d_out, int out_size) {
    const float* x     = (const float*)d_in[0];
    const float* off_w = (const float*)d_in[1];
    const float* off_b = (const float*)d_in[2];
    const float* w     = (const float*)d_in[3];
    const float* bias  = (const float*)d_in[4];
    const float* gamma = (const float*)d_in[5];
    const float* beta  = (const float*)d_in[6];
    float* out = (float*)d_out;

    cudaFuncSetAttribute(dcn_main_kernel,
                         cudaFuncAttributeMaxDynamicSharedMemorySize, SMEM_SZ);

    prep_kernel<<<144, 256>>>(w);
    off_conv_kernel<<<dim3(4, 8, 8), 256>>>(x, off_w, off_b);
    dcn_main_kernel<<<256, 256, SMEM_SZ>>>(x, bias);
    bn_relu_kernel<<<4096, 256>>>(out, gamma, beta);
}